// round 10
// baseline (speedup 1.0000x reference)
#include <cuda_runtime.h>
#include <math.h>

#define NROWS  4096
#define HALF   2048
#define DDIM   256
#define GROUPS 512   // NROWS / 8

__device__ float        g_groupsum[GROUPS];
__device__ unsigned int g_ticket;   // zero-initialized; reset by last block each run

__device__ __forceinline__ float warp_sum(float v) {
#pragma unroll
    for (int o = 16; o; o >>= 1) v += __shfl_xor_sync(0xFFFFFFFFu, v, o);
    return v;
}

__device__ __forceinline__ float logaddexp_f(float a, float b) {
    float m = fmaxf(a, b), n = fminf(a, b);
    return m + log1pf(expf(n - m));
}

// torchsort soft_rank (KL reg), row length 4, strength = 2.0.
// Literal implementation of the reference's min-max dual formula.
__device__ void soft_rank4(const float v[4], float out[4]) {
    float s[4];
    int perm[4] = {0, 1, 2, 3};
#pragma unroll
    for (int t = 0; t < 4; ++t) s[t] = v[t] * 0.5f;  // theta = v / strength

#define CSWAP(x, y)                                                     \
    if (s[x] < s[y]) {                                                  \
        float tf = s[x]; s[x] = s[y]; s[y] = tf;                        \
        int   ti = perm[x]; perm[x] = perm[y]; perm[y] = ti;            \
    }
    CSWAP(0, 1) CSWAP(2, 3) CSWAP(0, 2) CSWAP(1, 3) CSWAP(1, 2)
#undef CSWAP

    float lse_s[4][4];
#pragma unroll
    for (int i = 0; i < 4; ++i) {
        float L = s[i];
        lse_s[i][i] = L;
#pragma unroll
        for (int j = i + 1; j < 4; ++j) {
            L = logaddexp_f(L, s[j]);
            lse_s[i][j] = L;
        }
    }

    const float LW00 = 1.38629436f, LW01 = 1.94591015f, LW02 = 2.19722458f, LW03 = 2.30258509f;
    const float LW11 = 1.09861229f, LW12 = 1.60943791f, LW13 = 1.79175947f;
    const float LW22 = 0.69314718f, LW23 = 1.09861229f;
    const float LW33 = 0.0f;

    float B[4][4];
    B[0][0] = lse_s[0][0] - LW00; B[0][1] = lse_s[0][1] - LW01;
    B[0][2] = lse_s[0][2] - LW02; B[0][3] = lse_s[0][3] - LW03;
    B[1][1] = lse_s[1][1] - LW11; B[1][2] = lse_s[1][2] - LW12;
    B[1][3] = lse_s[1][3] - LW13;
    B[2][2] = lse_s[2][2] - LW22; B[2][3] = lse_s[2][3] - LW23;
    B[3][3] = lse_s[3][3] - LW33;

    float M[4][4];
#pragma unroll
    for (int i = 0; i < 4; ++i) {
        M[i][3] = B[i][3];
#pragma unroll
        for (int j = 2; j >= 0; --j)
            if (j >= i) M[i][j] = fmaxf(B[i][j], M[i][j + 1]);
    }

    float dual[4];
    dual[0] = M[0][0];
    dual[1] = fminf(M[0][1], M[1][1]);
    dual[2] = fminf(fminf(M[0][2], M[1][2]), M[2][2]);
    dual[3] = fminf(fminf(M[0][3], M[1][3]), fminf(M[2][3], M[3][3]));

#pragma unroll
    for (int k = 0; k < 4; ++k) out[perm[k]] = expf(s[k] - dual[k]);
}

__device__ __forceinline__ float spearman4(const float a[4], const float b[4]) {
    float ma = 0.25f * (a[0] + a[1] + a[2] + a[3]);
    float mb = 0.25f * (b[0] + b[1] + b[2] + b[3]);
    float na = 0.f, nb = 0.f, dp = 0.f;
#pragma unroll
    for (int t = 0; t < 4; ++t) {
        float x = a[t] - ma, y = b[t] - mb;
        na += x * x; nb += y * y; dp += x * y;
    }
    return dp * rsqrtf(na) * rsqrtf(nb);
}

// ---------------- fused kernel: one block per id-group of 8 rows -----------
// Group p owns rows {4p..4p+3} (half A) and {2048+4p..2048+4p+3} (half B).
// All 8 rows' positive-set distances are the 4x4 A-B cross-distance matrix.
// The LAST finishing block (ticket) reduces all group sums -> single scalar.
__global__ __launch_bounds__(256) void group_kernel(const float* __restrict__ f0,
                                                    const float* __restrict__ f1,
                                                    const float* __restrict__ f2,
                                                    float* __restrict__ out) {
    __shared__ float sh[3][8][DDIM];   // 24 KB: 8 rows x 3 features
    __shared__ float dist[3][4][4];    // dist[f][i][j] = ||A_i - B_j||
    __shared__ float rloss[8];
    __shared__ float red[256];
    __shared__ int   is_last;

    int p    = blockIdx.x;
    int tid  = threadIdx.x;
    int w    = tid >> 5;
    int lane = tid & 31;

    const float* Fs[3] = {f0, f1, f2};

    // Load 1536 float4 (24 KB), 6 per thread, coalesced per row-chunk.
#pragma unroll
    for (int u = 0; u < 6; ++u) {
        int idx = tid + u * 256;          // 0..1535
        int f   = idx >> 9;               // 512 float4 per feature
        int rem = idx & 511;
        int r   = rem >> 6;               // local row 0..7
        int c   = rem & 63;               // float4 column 0..63
        int grow = (r < 4) ? (4 * p + r) : (HALF + 4 * p + (r - 4));
        float4 v = ((const float4*)(Fs[f] + (size_t)grow * DDIM))[c];
        ((float4*)&sh[f][r][0])[c] = v;
    }
    __syncthreads();

    // 48 distances (3 features x 4x4 pairs), 6 per warp, sum of squared diffs.
#pragma unroll
    for (int t = 0; t < 6; ++t) {
        int d = w * 6 + t;
        int f = d >> 4, pair = d & 15, i = pair >> 2, j = pair & 3;
        const float4* A = (const float4*)&sh[f][i][0];
        const float4* B = (const float4*)&sh[f][4 + j][0];
        float4 a0 = A[lane], a1 = A[lane + 32];
        float4 b0 = B[lane], b1 = B[lane + 32];
        float dx0 = a0.x - b0.x, dy0 = a0.y - b0.y, dz0 = a0.z - b0.z, dw0 = a0.w - b0.w;
        float dx1 = a1.x - b1.x, dy1 = a1.y - b1.y, dz1 = a1.z - b1.z, dw1 = a1.w - b1.w;
        float s = dx0*dx0 + dy0*dy0 + dz0*dz0 + dw0*dw0
                + dx1*dx1 + dy1*dy1 + dz1*dz1 + dw1*dw1;
        s = warp_sum(s);
        if (lane == 0) dist[f][i][j] = sqrtf(fmaxf(s, 1e-12f));
    }
    __syncthreads();

    // Per-row tail: warp w owns local row w. Lanes 0-2 run the 3 soft-ranks
    // in parallel; shfl-gather; lane 0 does spearman.
    {
        int f = (lane < 3) ? lane : 0;
        float v[4], rr[4];
#pragma unroll
        for (int k = 0; k < 4; ++k)
            v[k] = (w < 4) ? dist[f][w][k] : dist[f][k][w - 4];
        soft_rank4(v, rr);

        float r0[4], r1[4], r2[4];
#pragma unroll
        for (int k = 0; k < 4; ++k) {
            r0[k] = __shfl_sync(0xFFFFFFFFu, rr[k], 0);
            r1[k] = __shfl_sync(0xFFFFFFFFu, rr[k], 1);
            r2[k] = __shfl_sync(0xFFFFFFFFu, rr[k], 2);
        }
        if (lane == 0) {
            float c01 = spearman4(r0, r1);
            float c02 = spearman4(r0, r2);
            float c12 = spearman4(r1, r2);
            rloss[w] = (c01 + c02 + c12 + 3.0f) * (1.0f / 6.0f);
        }
    }
    __syncthreads();

    // Publish group sum; last-arriving block performs the final reduction.
    if (tid == 0) {
        float s = rloss[0] + rloss[1] + rloss[2] + rloss[3]
                + rloss[4] + rloss[5] + rloss[6] + rloss[7];
        g_groupsum[p] = s;
        __threadfence();                         // make sum visible before ticket
        unsigned int t = atomicAdd(&g_ticket, 1u);
        is_last = (t == GROUPS - 1);
    }
    __syncthreads();

    if (is_last) {
        // Deterministic fixed-order tree reduction of the 512 group sums.
        float v = g_groupsum[tid] + g_groupsum[tid + 256];
        red[tid] = v;
        __syncthreads();
#pragma unroll
        for (int o = 128; o; o >>= 1) {
            if (tid < o) red[tid] += red[tid + o];
            __syncthreads();
        }
        if (tid == 0) {
            out[0]   = red[0] * (1.0f / NROWS);
            g_ticket = 0;                        // reset for next graph replay
        }
    }
}

extern "C" void kernel_launch(void* const* d_in, const int* in_sizes, int n_in,
                              void* d_out, int out_size) {
    const float* f0 = (const float*)d_in[0];
    const float* f1 = (const float*)d_in[1];
    const float* f2 = (const float*)d_in[2];
    (void)in_sizes; (void)n_in; (void)out_size;

    group_kernel<<<GROUPS, 256>>>(f0, f1, f2, (float*)d_out);
}

// round 11
// speedup vs baseline: 1.0025x; 1.0025x over previous
#include <cuda_runtime.h>
#include <math.h>

#define NROWS  4096
#define HALF   2048
#define DDIM   256
#define GROUPS 512            // NROWS / 8
#define NBLK   (GROUPS * 3)   // one block per (group, feature)

// Scratch (device globals; zero-initialized once, tickets self-reset per run)
__device__ float        g_dist[GROUPS * 48];   // [p][f][i*4+j]
__device__ float        g_groupsum[GROUPS];
__device__ unsigned int g_gtick[GROUPS];       // per-group arrival counter
__device__ unsigned int g_ticket;              // global arrival counter

__device__ __forceinline__ float warp_sum(float v) {
#pragma unroll
    for (int o = 16; o; o >>= 1) v += __shfl_xor_sync(0xFFFFFFFFu, v, o);
    return v;
}

// torchsort soft_rank (KL reg), n=4, strength=2 — log-free ratio form.
// Reference: B = LSE(s[i..j]) - LSE(logw[i..j]); dual_k = min_{i<=k} max_{j>=k} B;
// rank = exp(s - dual). Since log is monotone, do max/min on R = Ssum/Wsum:
// rank_k = E_k / (min_i max_j R[i][j]),  E_k = exp(s_k - s_0) (shift-invariant).
__device__ __forceinline__ void soft_rank4(const float v[4], float out[4]) {
    float s[4];
    int perm[4] = {0, 1, 2, 3};
#pragma unroll
    for (int t = 0; t < 4; ++t) s[t] = v[t] * 0.5f;   // theta = v / strength

#define CSWAP(x, y)                                                     \
    if (s[x] < s[y]) {                                                  \
        float tf = s[x]; s[x] = s[y]; s[y] = tf;                        \
        int   ti = perm[x]; perm[x] = perm[y]; perm[y] = ti;            \
    }
    CSWAP(0, 1) CSWAP(2, 3) CSWAP(0, 2) CSWAP(1, 3) CSWAP(1, 2)
#undef CSWAP

    // exps relative to the max element (s[0] after sort) — E0 == 1
    float E0 = 1.0f;
    float E1 = __expf(s[1] - s[0]);
    float E2 = __expf(s[2] - s[0]);
    float E3 = __expf(s[3] - s[0]);

    // segment sums of E
    float S01 = E0 + E1, S12 = E1 + E2, S23 = E2 + E3;
    float S02 = S01 + E2, S13 = S12 + E3, S03 = S02 + E3;

    // ratios Ssum/Wsum, w = [4,3,2,1] -> Wsum: 4,7,9,10 / 3,5,6 / 2,3 / 1
    float B00 = E0  * 0.25f;
    float B01 = S01 * (1.0f / 7.0f);
    float B02 = S02 * (1.0f / 9.0f);
    float B03 = S03 * 0.1f;
    float B11 = E1  * (1.0f / 3.0f);
    float B12 = S12 * 0.2f;
    float B13 = S13 * (1.0f / 6.0f);
    float B22 = E2  * 0.5f;
    float B23 = S23 * (1.0f / 3.0f);
    float B33 = E3;

    // suffix max over j, then min over i<=k
    float M03 = B03, M02 = fmaxf(B02, M03), M01 = fmaxf(B01, M02), M00 = fmaxf(B00, M01);
    float M13 = B13, M12 = fmaxf(B12, M13), M11 = fmaxf(B11, M12);
    float M23 = B23, M22 = fmaxf(B22, M23);
    float M33 = B33;

    float R0 = M00;
    float R1 = fminf(M01, M11);
    float R2 = fminf(fminf(M02, M12), M22);
    float R3 = fminf(fminf(M03, M13), fminf(M23, M33));

    out[perm[0]] = __fdividef(E0, R0);
    out[perm[1]] = __fdividef(E1, R1);
    out[perm[2]] = __fdividef(E2, R2);
    out[perm[3]] = __fdividef(E3, R3);
}

__device__ __forceinline__ float spearman4(const float a[4], const float b[4]) {
    float ma = 0.25f * (a[0] + a[1] + a[2] + a[3]);
    float mb = 0.25f * (b[0] + b[1] + b[2] + b[3]);
    float na = 0.f, nb = 0.f, dp = 0.f;
#pragma unroll
    for (int t = 0; t < 4; ++t) {
        float x = a[t] - ma, y = b[t] - mb;
        na += x * x; nb += y * y; dp += x * y;
    }
    return dp * rsqrtf(na) * rsqrtf(nb);
}

// One block per (group p, feature f). Computes the 4x4 A-B cross-distance
// matrix for its feature; the 3rd-arriving block per group runs the 8-row
// tail; the 512th tail-finisher does the final deterministic mean.
__global__ __launch_bounds__(128) void fused_kernel(const float* __restrict__ f0,
                                                    const float* __restrict__ f1,
                                                    const float* __restrict__ f2,
                                                    float* __restrict__ out) {
    __shared__ float sh[8][DDIM];     // 8 KB: this feature's 8 rows
    __shared__ float rloss[8];
    __shared__ float red[128];
    __shared__ int   flag1, flag2;

    int b    = blockIdx.x;
    int p    = b / 3;
    int f    = b - 3 * p;
    int tid  = threadIdx.x;
    int w    = tid >> 5;
    int lane = tid & 31;

    const float* F = (f == 0) ? f0 : (f == 1) ? f1 : f2;

    // ---- load 8 rows (512 float4), 4 per thread, coalesced ----
#pragma unroll
    for (int u = 0; u < 4; ++u) {
        int idx = tid + u * 128;                 // 0..511
        int r   = idx >> 6;                      // local row 0..7
        int c   = idx & 63;                      // float4 col
        int grow = (r < 4) ? (4 * p + r) : (HALF + 4 * p + (r - 4));
        ((float4*)&sh[r][0])[c] = ((const float4*)(F + (size_t)grow * DDIM))[c];
    }
    __syncthreads();

    // ---- 16 distances: warp w = row A_w vs B_0..3 ----
    float* dst = &g_dist[p * 48 + f * 16];
    {
        const float4* A = (const float4*)&sh[w][0];
        float4 a0 = A[lane], a1 = A[lane + 32];
#pragma unroll
        for (int j = 0; j < 4; ++j) {
            const float4* B = (const float4*)&sh[4 + j][0];
            float4 b0 = B[lane], b1 = B[lane + 32];
            float dx0 = a0.x-b0.x, dy0 = a0.y-b0.y, dz0 = a0.z-b0.z, dw0 = a0.w-b0.w;
            float dx1 = a1.x-b1.x, dy1 = a1.y-b1.y, dz1 = a1.z-b1.z, dw1 = a1.w-b1.w;
            float s = dx0*dx0 + dy0*dy0 + dz0*dz0 + dw0*dw0
                    + dx1*dx1 + dy1*dy1 + dz1*dz1 + dw1*dw1;
            s = warp_sum(s);
            if (lane == 0) dst[w * 4 + j] = sqrtf(fmaxf(s, 1e-12f));
        }
    }

    // ---- per-group ticket: 3rd arriver runs the tail ----
    __threadfence();                  // every storing thread: release its STGs
    __syncthreads();
    if (tid == 0) {
        unsigned int t = atomicAdd(&g_gtick[p], 1u);
        flag1 = (t == 2u);
    }
    __syncthreads();
    if (!flag1) return;

    // ---- tail: 8 rows, warp w handles local rows 2w, 2w+1 ----
    {
        int half = lane >> 4;                    // 0/1 -> which of the two rows
        int sub  = lane & 15;
        int r    = 2 * w + half;                 // local row 0..7
        int fi   = (sub < 3) ? sub : 0;          // lanes 0-2 per half: the 3 features
        const float* dd = &g_dist[p * 48 + fi * 16];
        float v[4], rr[4];
#pragma unroll
        for (int k = 0; k < 4; ++k)
            v[k] = (r < 4) ? dd[r * 4 + k] : dd[k * 4 + (r - 4)];
        soft_rank4(v, rr);

        int base = lane & 16;                    // half-warp base
        float r0[4], r1[4], r2[4];
#pragma unroll
        for (int k = 0; k < 4; ++k) {
            r0[k] = __shfl_sync(0xFFFFFFFFu, rr[k], base + 0);
            r1[k] = __shfl_sync(0xFFFFFFFFu, rr[k], base + 1);
            r2[k] = __shfl_sync(0xFFFFFFFFu, rr[k], base + 2);
        }
        if (sub == 0) {
            float c01 = spearman4(r0, r1);
            float c02 = spearman4(r0, r2);
            float c12 = spearman4(r1, r2);
            rloss[r] = (c01 + c02 + c12 + 3.0f) * (1.0f / 6.0f);
        }
    }
    __syncthreads();

    // ---- publish group sum; 512th group-finisher reduces everything ----
    if (tid == 0) {
        float s = rloss[0] + rloss[1] + rloss[2] + rloss[3]
                + rloss[4] + rloss[5] + rloss[6] + rloss[7];
        g_groupsum[p] = s;
        g_gtick[p]    = 0;                       // reset for next graph replay
        __threadfence();
        unsigned int t = atomicAdd(&g_ticket, 1u);
        flag2 = (t == GROUPS - 1);
    }
    __syncthreads();
    if (!flag2) return;

    // deterministic fixed-order tree over 512 group sums
    float v = g_groupsum[tid] + g_groupsum[tid + 128]
            + g_groupsum[tid + 256] + g_groupsum[tid + 384];
    red[tid] = v;
    __syncthreads();
#pragma unroll
    for (int o = 64; o; o >>= 1) {
        if (tid < o) red[tid] += red[tid + o];
        __syncthreads();
    }
    if (tid == 0) {
        out[0]   = red[0] * (1.0f / NROWS);
        g_ticket = 0;                            // reset for next graph replay
    }
}

extern "C" void kernel_launch(void* const* d_in, const int* in_sizes, int n_in,
                              void* d_out, int out_size) {
    const float* f0 = (const float*)d_in[0];
    const float* f1 = (const float*)d_in[1];
    const float* f2 = (const float*)d_in[2];
    (void)in_sizes; (void)n_in; (void)out_size;

    fused_kernel<<<NBLK, 128>>>(f0, f1, f2, (float*)d_out);
}